// round 3
// baseline (speedup 1.0000x reference)
#include <cuda_runtime.h>
#include <float.h>

#define B_   8
#define C_   64
#define N_   4096
#define K_   20
#define M_   8
#define OUTC 64
#define CM   512          // C_*M_
#define PTS  (B_*N_)      // 32768

// Scratch (allocation-free rule: __device__ globals)
__device__ float g_ft[B_*N_*C_];          // feature transposed: [b][n][c]   (8 MB)
__device__ float g_aggT[CM*(size_t)PTS];  // agg transposed:     [j][pt]     (64 MB)
__device__ float g_wT[CM*OUTC];           // conv_w transposed:  [j][oc]     (128 KB)

// ---------------------------------------------------------------------------
// K1: feature (B,C,N) -> g_ft (B,N,C), tiled 32x32 transpose
// ---------------------------------------------------------------------------
__global__ void k_transpose_feat(const float* __restrict__ feat) {
    __shared__ float tile[32][33];
    const int b  = blockIdx.z;
    const int c0 = blockIdx.y * 32;
    const int n0 = blockIdx.x * 32;
    const int tx = threadIdx.x, ty = threadIdx.y;   // block (32,8)
    const float* fb = feat + (size_t)b * C_ * N_;
    #pragma unroll
    for (int r = 0; r < 4; r++) {
        tile[ty + 8*r][tx] = fb[(size_t)(c0 + ty + 8*r) * N_ + (n0 + tx)];
    }
    __syncthreads();
    float* ob = g_ft + (size_t)b * N_ * C_;
    #pragma unroll
    for (int r = 0; r < 4; r++) {
        ob[(size_t)(n0 + ty + 8*r) * C_ + (c0 + tx)] = tile[tx][ty + 8*r];
    }
}

// ---------------------------------------------------------------------------
// K2: conv_w (OUTC, CM) -> g_wT (CM, OUTC)
// ---------------------------------------------------------------------------
__global__ void k_transpose_w(const float* __restrict__ w) {
    int i = blockIdx.x * blockDim.x + threadIdx.x;   // i = j*64 + oc
    if (i < CM * OUTC) {
        int j  = i >> 6;
        int oc = i & 63;
        g_wT[i] = w[oc * CM + j];
    }
}

// ---------------------------------------------------------------------------
// K3: warp-per-point: perm matrix + softmax + aggregation -> g_aggT[j][pt]
//     8 points per 256-thread block
// ---------------------------------------------------------------------------
__global__ void __launch_bounds__(256) k_agg(
    const float* __restrict__ x,
    const int* __restrict__ nidx,          // int32 (JAX x64 disabled!)
    const float* __restrict__ kern)
{
    const int warp = threadIdx.x >> 5;
    const int lane = threadIdx.x & 31;
    const int pt0  = blockIdx.x * 8;
    const int pt   = pt0 + warp;
    const int b    = pt >> 12;        // N_ = 4096

    __shared__ int   idx_s[8][20];
    __shared__ float p_s[8][20][8];          // softmaxed perm matrix
    __shared__ float agg_s[8][CM];           // [pt-in-block][j]

    // ---- indices + x gather (lanes 0..19) ----
    float px[8];
    float x0 = 0.f, x1 = 0.f, x2 = 0.f;
    if (lane < K_) {
        int ik = nidx[pt * K_ + lane] & (N_ - 1);
        idx_s[warp][lane] = ik;
        const float* xb = x + (size_t)b * 3 * N_;
        x0 = xb[ik];
        x1 = xb[N_ + ik];
        x2 = xb[2*N_ + ik];
    }
    // relative to neighbor 0
    const float r0 = x0 - __shfl_sync(0xFFFFFFFFu, x0, 0);
    const float r1 = x1 - __shfl_sync(0xFFFFFFFFu, x1, 0);
    const float r2 = x2 - __shfl_sync(0xFFFFFFFFu, x2, 0);

    #pragma unroll
    for (int m = 0; m < M_; m++) {
        float v = r0 * kern[m] + r1 * kern[M_ + m] + r2 * kern[2*M_ + m];
        if (lane == 0 && m == 0) v += 1.0f;       // one_pad
        px[m] = (lane < K_) ? v : -FLT_MAX;
    }

    // ---- softmax over k (20 lanes) per m ----
    #pragma unroll
    for (int m = 0; m < M_; m++) {
        float mx = px[m];
        #pragma unroll
        for (int o = 16; o > 0; o >>= 1)
            mx = fmaxf(mx, __shfl_xor_sync(0xFFFFFFFFu, mx, o));
        float e = (lane < K_) ? __expf(px[m] - mx) : 0.f;
        float s = e;
        #pragma unroll
        for (int o = 16; o > 0; o >>= 1)
            s += __shfl_xor_sync(0xFFFFFFFFu, s, o);
        px[m] = e * (1.0f / s);
    }
    if (lane < K_) {
        float4* dst = (float4*)p_s[warp][lane];
        dst[0] = make_float4(px[0], px[1], px[2], px[3]);
        dst[1] = make_float4(px[4], px[5], px[6], px[7]);
    }
    __syncwarp();

    // ---- aggregation: each lane owns channels c0, c0+1 ----
    const int c0 = lane * 2;
    float acc0[8] = {0,0,0,0,0,0,0,0};
    float acc1[8] = {0,0,0,0,0,0,0,0};
    const float* ftb = g_ft + (size_t)b * N_ * C_;
    #pragma unroll
    for (int k = 0; k < K_; k++) {
        const int ii = idx_s[warp][k];
        const float2 f = *(const float2*)(ftb + (size_t)ii * C_ + c0);
        const float4* pp = (const float4*)p_s[warp][k];
        const float4 pA = pp[0], pB = pp[1];
        acc0[0] += f.x * pA.x;  acc0[1] += f.x * pA.y;
        acc0[2] += f.x * pA.z;  acc0[3] += f.x * pA.w;
        acc0[4] += f.x * pB.x;  acc0[5] += f.x * pB.y;
        acc0[6] += f.x * pB.z;  acc0[7] += f.x * pB.w;
        acc1[0] += f.y * pA.x;  acc1[1] += f.y * pA.y;
        acc1[2] += f.y * pA.z;  acc1[3] += f.y * pA.w;
        acc1[4] += f.y * pB.x;  acc1[5] += f.y * pB.y;
        acc1[6] += f.y * pB.z;  acc1[7] += f.y * pB.w;
    }
    // stage to smem: agg_s[warp][c*M + m]
    {
        float4* dst = (float4*)&agg_s[warp][c0 * M_];
        dst[0] = make_float4(acc0[0], acc0[1], acc0[2], acc0[3]);
        dst[1] = make_float4(acc0[4], acc0[5], acc0[6], acc0[7]);
        dst[2] = make_float4(acc1[0], acc1[1], acc1[2], acc1[3]);
        dst[3] = make_float4(acc1[4], acc1[5], acc1[6], acc1[7]);
    }
    __syncthreads();

    // ---- transposed write: g_aggT[j][pt0..pt0+7], 2 rows per thread ----
    const int t = threadIdx.x;
    #pragma unroll
    for (int rr = 0; rr < 2; rr++) {
        const int j = t * 2 + rr;
        float v[8];
        #pragma unroll
        for (int w = 0; w < 8; w++) v[w] = agg_s[w][j];
        float4* dst = (float4*)(g_aggT + (size_t)j * PTS + pt0);
        dst[0] = make_float4(v[0], v[1], v[2], v[3]);
        dst[1] = make_float4(v[4], v[5], v[6], v[7]);
    }
}

// ---------------------------------------------------------------------------
// K4: GEMM out[pt][oc] = aggT^T @ wT + bias, lrelu, + feature residual
//     TM=128 pts, TN=64 oc, KC=64, 256 threads, micro 8pt x 4oc
// ---------------------------------------------------------------------------
__global__ void __launch_bounds__(256) k_gemm(
    const float* __restrict__ bias,
    const float* __restrict__ feat,
    float* __restrict__ out)
{
    __shared__ float aS[64 * 128];   // [k][pt]
    __shared__ float wS[64 * 64];    // [k][oc]

    const int t  = threadIdx.x;
    const int tx = t & 15;           // pt direction
    const int ty = t >> 4;           // oc direction (0..15)
    const int ptBase = blockIdx.x * 128;

    float acc[8][4];
    #pragma unroll
    for (int i = 0; i < 8; i++)
        #pragma unroll
        for (int j = 0; j < 4; j++) acc[i][j] = 0.f;

    for (int kc = 0; kc < CM; kc += 64) {
        // load aS: 64x128 floats = 2048 float4
        #pragma unroll
        for (int i = 0; i < 8; i++) {
            const int f4   = t + i * 256;
            const int row  = f4 >> 5;        // 32 float4 per 128-col row
            const int col4 = f4 & 31;
            ((float4*)aS)[f4] =
                *(const float4*)(g_aggT + (size_t)(kc + row) * PTS + ptBase + col4 * 4);
        }
        // load wS: 64x64 floats = 1024 float4
        #pragma unroll
        for (int i = 0; i < 4; i++) {
            const int f4   = t + i * 256;
            const int row  = f4 >> 4;
            const int col4 = f4 & 15;
            ((float4*)wS)[f4] =
                *(const float4*)(g_wT + (size_t)(kc + row) * OUTC + col4 * 4);
        }
        __syncthreads();

        #pragma unroll 16
        for (int k = 0; k < 64; k++) {
            float a[8];
            #pragma unroll
            for (int i = 0; i < 8; i++) a[i] = aS[k * 128 + tx + 16 * i];
            const float4 w4 = *(const float4*)&wS[k * 64 + ty * 4];
            #pragma unroll
            for (int i = 0; i < 8; i++) {
                acc[i][0] += a[i] * w4.x;
                acc[i][1] += a[i] * w4.y;
                acc[i][2] += a[i] * w4.z;
                acc[i][3] += a[i] * w4.w;
            }
        }
        __syncthreads();
    }

    // epilogue: bias + leaky_relu + residual, store (b, oc, n)
    const float4 b4 = *(const float4*)&bias[ty * 4];
    const float bb[4] = {b4.x, b4.y, b4.z, b4.w};
    #pragma unroll
    for (int i = 0; i < 8; i++) {
        const int pt = ptBase + tx + 16 * i;
        const int b  = pt >> 12;
        const int n  = pt & (N_ - 1);
        #pragma unroll
        for (int j = 0; j < 4; j++) {
            const int oc = ty * 4 + j;
            float v = acc[i][j] + bb[j];
            v = (v > 0.f) ? v : 0.2f * v;
            const size_t o = ((size_t)(b * OUTC + oc)) * N_ + n;
            out[o] = v + feat[o];
        }
    }
}

// ---------------------------------------------------------------------------
extern "C" void kernel_launch(void* const* d_in, const int* in_sizes, int n_in,
                              void* d_out, int out_size) {
    const float* x    = (const float*)d_in[0];
    const float* feat = (const float*)d_in[1];
    const int*   nidx = (const int*)d_in[2];     // int32: JAX x64 is disabled
    const float* kern = (const float*)d_in[3];
    const float* w    = (const float*)d_in[4];
    const float* bias = (const float*)d_in[5];
    float* out = (float*)d_out;

    k_transpose_feat<<<dim3(N_/32, C_/32, B_), dim3(32, 8)>>>(feat);
    k_transpose_w<<<(CM*OUTC + 255)/256, 256>>>(w);
    k_agg<<<PTS/8, 256>>>(x, nidx, kern);
    k_gemm<<<PTS/128, 256>>>(bias, feat, out);
}

// round 5
// speedup vs baseline: 2.1320x; 2.1320x over previous
#include <cuda_runtime.h>
#include <cuda_fp16.h>
#include <float.h>
#include <cstdint>

#define B_   8
#define C_   64
#define N_   4096
#define K_   20
#define M_   8
#define OUTC 64
#define CM   512          // C_*M_
#define PTS  (B_*N_)      // 32768

// Scratch (allocation-free rule: __device__ globals)
__device__ float g_ft[B_*N_*C_];                           // feature [b][n][c]
__device__ __align__(16) __half g_aggH[(size_t)PTS*CM];    // agg fp16 [pt][j]  (32 MB)
__device__ __align__(16) __half g_wh[CM*OUTC];             // conv_w fp16 [oc][j] (64 KB)

__device__ __forceinline__ uint32_t smem_u32(const void* p) {
    uint32_t a;
    asm("{ .reg .u64 t; cvta.to.shared.u64 t, %1; cvt.u32.u64 %0, t; }" : "=r"(a) : "l"(p));
    return a;
}

// ===========================================================================
// K1: feature (B,C,N) -> g_ft (B,N,C)
// ===========================================================================
__global__ void k_transpose_feat(const float* __restrict__ feat) {
    __shared__ float tile[32][33];
    const int b  = blockIdx.z;
    const int c0 = blockIdx.y * 32;
    const int n0 = blockIdx.x * 32;
    const int tx = threadIdx.x, ty = threadIdx.y;   // block (32,8)
    const float* fb = feat + (size_t)b * C_ * N_;
    #pragma unroll
    for (int r = 0; r < 4; r++)
        tile[ty + 8*r][tx] = fb[(size_t)(c0 + ty + 8*r) * N_ + (n0 + tx)];
    __syncthreads();
    float* ob = g_ft + (size_t)b * N_ * C_;
    #pragma unroll
    for (int r = 0; r < 4; r++)
        ob[(size_t)(n0 + ty + 8*r) * C_ + (c0 + tx)] = tile[tx][ty + 8*r];
}

// ===========================================================================
// K2: conv_w fp32 [oc][j] -> fp16 g_wh (same layout)
// ===========================================================================
__global__ void k_prep_w(const float* __restrict__ w) {
    int i = blockIdx.x * blockDim.x + threadIdx.x;
    if (i < CM * OUTC) g_wh[i] = __float2half(w[i]);
}

// ===========================================================================
// K3: warp-per-point: perm matrix + softmax + aggregation -> g_aggH[pt][j]
// ===========================================================================
__global__ void __launch_bounds__(256) k_agg(
    const float* __restrict__ x,
    const int* __restrict__ nidx,          // int32 (JAX x64 disabled)
    const float* __restrict__ kern)
{
    const int warp = threadIdx.x >> 5;
    const int lane = threadIdx.x & 31;
    const int pt   = blockIdx.x * 8 + warp;
    const int b    = pt >> 12;

    __shared__ int   idx_s[8][20];
    __shared__ float p_s[8][20][8];

    float px[8];
    float x0 = 0.f, x1 = 0.f, x2 = 0.f;
    if (lane < K_) {
        int ik = nidx[pt * K_ + lane] & (N_ - 1);
        idx_s[warp][lane] = ik;
        const float* xb = x + (size_t)b * 3 * N_;
        x0 = xb[ik];
        x1 = xb[N_ + ik];
        x2 = xb[2*N_ + ik];
    }
    const float r0 = x0 - __shfl_sync(0xFFFFFFFFu, x0, 0);
    const float r1 = x1 - __shfl_sync(0xFFFFFFFFu, x1, 0);
    const float r2 = x2 - __shfl_sync(0xFFFFFFFFu, x2, 0);

    #pragma unroll
    for (int m = 0; m < M_; m++) {
        float v = r0 * kern[m] + r1 * kern[M_ + m] + r2 * kern[2*M_ + m];
        if (lane == 0 && m == 0) v += 1.0f;       // one_pad
        px[m] = (lane < K_) ? v : -FLT_MAX;
    }

    #pragma unroll
    for (int m = 0; m < M_; m++) {
        float mx = px[m];
        #pragma unroll
        for (int o = 16; o > 0; o >>= 1)
            mx = fmaxf(mx, __shfl_xor_sync(0xFFFFFFFFu, mx, o));
        float e = (lane < K_) ? __expf(px[m] - mx) : 0.f;
        float s = e;
        #pragma unroll
        for (int o = 16; o > 0; o >>= 1)
            s += __shfl_xor_sync(0xFFFFFFFFu, s, o);
        px[m] = e * (1.0f / s);
    }
    if (lane < K_) {
        float4* dst = (float4*)p_s[warp][lane];
        dst[0] = make_float4(px[0], px[1], px[2], px[3]);
        dst[1] = make_float4(px[4], px[5], px[6], px[7]);
    }
    __syncwarp();

    // aggregation: lane owns channels 2*lane, 2*lane+1
    const int c0 = lane * 2;
    float acc0[8] = {0,0,0,0,0,0,0,0};
    float acc1[8] = {0,0,0,0,0,0,0,0};
    const float* ftb = g_ft + (size_t)b * N_ * C_;
    #pragma unroll
    for (int k = 0; k < K_; k++) {
        const int ii = idx_s[warp][k];
        const float2 f = *(const float2*)(ftb + (size_t)ii * C_ + c0);
        const float4* pp = (const float4*)p_s[warp][k];
        const float4 pA = pp[0], pB = pp[1];
        acc0[0] += f.x * pA.x;  acc0[1] += f.x * pA.y;
        acc0[2] += f.x * pA.z;  acc0[3] += f.x * pA.w;
        acc0[4] += f.x * pB.x;  acc0[5] += f.x * pB.y;
        acc0[6] += f.x * pB.z;  acc0[7] += f.x * pB.w;
        acc1[0] += f.y * pA.x;  acc1[1] += f.y * pA.y;
        acc1[2] += f.y * pA.z;  acc1[3] += f.y * pA.w;
        acc1[4] += f.y * pB.x;  acc1[5] += f.y * pB.y;
        acc1[6] += f.y * pB.z;  acc1[7] += f.y * pB.w;
    }

    // fp16 pack: lane's 16 values are j = 16*lane .. 16*lane+15
    __half2 h0[4], h1[4];
    #pragma unroll
    for (int i = 0; i < 4; i++) {
        h0[i] = __floats2half2_rn(acc0[2*i], acc0[2*i+1]);
        h1[i] = __floats2half2_rn(acc1[2*i], acc1[2*i+1]);
    }
    __half* dst = g_aggH + (size_t)pt * CM + 16 * lane;
    *(uint4*)(dst)     = *(uint4*)h0;
    *(uint4*)(dst + 8) = *(uint4*)h1;
}

// ===========================================================================
// K4: HMMA fp16 GEMM (mma.sync m16n8k16): out = aggH @ wh^T + bias, lrelu, +feat
//     block tile 128 pt x 64 oc, 8 warps (4 m x 2 n), warp tile 32x32
// ===========================================================================
#define AS_STRIDE 72     // halves per A smem row (64 + 8 pad)
#define BS_STRIDE 72
#define OS_STRIDE 132    // floats per o smem row (128 + 4 pad)

__global__ void __launch_bounds__(256) k_gemm_hmma(
    const float* __restrict__ bias,
    const float* __restrict__ feat,
    float* __restrict__ out)
{
    __shared__ union {
        struct { __half a[128 * AS_STRIDE]; __half b[64 * BS_STRIDE]; } ld;
        float o[64 * OS_STRIDE];
    } sm;

    const int tid  = threadIdx.x;
    const int wid  = tid >> 5;
    const int lane = tid & 31;
    const int warp_m = (wid & 3) * 32;   // 4 warps over 128 pts
    const int warp_n = (wid >> 2) * 32;  // 2 warps over 64 ocs
    const int ptBase = blockIdx.x * 128;

    float acc[2][4][4];
    #pragma unroll
    for (int mi = 0; mi < 2; mi++)
        #pragma unroll
        for (int ni = 0; ni < 4; ni++)
            #pragma unroll
            for (int r = 0; r < 4; r++) acc[mi][ni][r] = 0.f;

    const __half* aSrc = g_aggH + (size_t)ptBase * CM;

    for (int kc = 0; kc < CM; kc += 64) {
        // ---- load A chunk: 128 rows x 64 halves (1024 uint4) ----
        #pragma unroll
        for (int i = 0; i < 4; i++) {
            const int c   = tid + i * 256;
            const int row = c >> 3;
            const int c8  = c & 7;
            *(uint4*)(sm.ld.a + row * AS_STRIDE + c8 * 8) =
                *(const uint4*)(aSrc + (size_t)row * CM + kc + c8 * 8);
        }
        // ---- load B chunk: 64 rows x 64 halves (512 uint4) ----
        #pragma unroll
        for (int i = 0; i < 2; i++) {
            const int c   = tid + i * 256;
            const int row = c >> 3;
            const int c8  = c & 7;
            *(uint4*)(sm.ld.b + row * BS_STRIDE + c8 * 8) =
                *(const uint4*)(g_wh + (size_t)row * CM + kc + c8 * 8);
        }
        __syncthreads();

        #pragma unroll
        for (int ks = 0; ks < 4; ks++) {
            // A fragments: 2 m-subtiles, ldmatrix.x4
            uint32_t a[2][4];
            #pragma unroll
            for (int mi = 0; mi < 2; mi++) {
                const uint32_t addr = smem_u32(
                    sm.ld.a + (warp_m + mi * 16 + (lane & 15)) * AS_STRIDE
                            + ks * 16 + (lane >> 4) * 8);
                asm volatile("ldmatrix.sync.aligned.m8n8.x4.shared.b16 "
                             "{%0,%1,%2,%3}, [%4];"
                             : "=r"(a[mi][0]), "=r"(a[mi][1]),
                               "=r"(a[mi][2]), "=r"(a[mi][3])
                             : "r"(addr));
            }
            // B fragments: 4 n-subtiles, ldmatrix.x2 (non-trans: [n][k] rows
            // give k-consecutive pairs at fixed n == mma col-major B frag)
            uint32_t bfr[4][2];
            #pragma unroll
            for (int ni = 0; ni < 4; ni++) {
                const uint32_t addr = smem_u32(
                    sm.ld.b + (warp_n + ni * 8 + (lane & 7)) * BS_STRIDE
                            + ks * 16 + ((lane >> 3) & 1) * 8);
                asm volatile("ldmatrix.sync.aligned.m8n8.x2.shared.b16 "
                             "{%0,%1}, [%2];"
                             : "=r"(bfr[ni][0]), "=r"(bfr[ni][1])
                             : "r"(addr));
            }
            #pragma unroll
            for (int mi = 0; mi < 2; mi++)
                #pragma unroll
                for (int ni = 0; ni < 4; ni++) {
                    asm volatile(
                        "mma.sync.aligned.m16n8k16.row.col.f32.f16.f16.f32 "
                        "{%0,%1,%2,%3}, {%4,%5,%6,%7}, {%8,%9}, {%0,%1,%2,%3};"
                        : "+f"(acc[mi][ni][0]), "+f"(acc[mi][ni][1]),
                          "+f"(acc[mi][ni][2]), "+f"(acc[mi][ni][3])
                        : "r"(a[mi][0]), "r"(a[mi][1]), "r"(a[mi][2]), "r"(a[mi][3]),
                          "r"(bfr[ni][0]), "r"(bfr[ni][1]));
                }
        }
        __syncthreads();
    }

    // ---- scatter fragments to smem as [oc][pt] ----
    {
        const int r  = lane >> 2;
        const int cp = (lane & 3) * 2;
        #pragma unroll
        for (int mi = 0; mi < 2; mi++)
            #pragma unroll
            for (int ni = 0; ni < 4; ni++) {
                const int pt0 = warp_m + mi * 16 + r;
                const int oc0 = warp_n + ni * 8 + cp;
                sm.o[oc0 * OS_STRIDE + pt0]           = acc[mi][ni][0];
                sm.o[(oc0 + 1) * OS_STRIDE + pt0]     = acc[mi][ni][1];
                sm.o[oc0 * OS_STRIDE + pt0 + 8]       = acc[mi][ni][2];
                sm.o[(oc0 + 1) * OS_STRIDE + pt0 + 8] = acc[mi][ni][3];
            }
    }
    __syncthreads();

    // ---- fused epilogue: bias + leaky_relu + residual, coalesced stores ----
    const int b = ptBase >> 12;            // whole tile within one batch
    const int n0 = ptBase & (N_ - 1);
    #pragma unroll
    for (int i = 0; i < 8; i++) {
        const int c    = tid + i * 256;    // 2048 float4 tasks
        const int oc   = c >> 5;
        const int col4 = (c & 31) * 4;
        const float* src = sm.o + oc * OS_STRIDE + col4;
        const size_t o = ((size_t)(b * OUTC + oc)) * N_ + n0 + col4;
        const float4 f = *(const float4*)(feat + o);
        const float bb = bias[oc];
        float4 v;
        v.x = src[0] + bb; v.x = (v.x > 0.f ? v.x : 0.2f * v.x) + f.x;
        v.y = src[1] + bb; v.y = (v.y > 0.f ? v.y : 0.2f * v.y) + f.y;
        v.z = src[2] + bb; v.z = (v.z > 0.f ? v.z : 0.2f * v.z) + f.z;
        v.w = src[3] + bb; v.w = (v.w > 0.f ? v.w : 0.2f * v.w) + f.w;
        *(float4*)(out + o) = v;
    }
}

// ===========================================================================
extern "C" void kernel_launch(void* const* d_in, const int* in_sizes, int n_in,
                              void* d_out, int out_size) {
    const float* x    = (const float*)d_in[0];
    const float* feat = (const float*)d_in[1];
    const int*   nidx = (const int*)d_in[2];     // int32: JAX x64 is disabled
    const float* kern = (const float*)d_in[3];
    const float* w    = (const float*)d_in[4];
    const float* bias = (const float*)d_in[5];
    float* out = (float*)d_out;

    k_transpose_feat<<<dim3(N_/32, C_/32, B_), dim3(32, 8)>>>(feat);
    k_prep_w<<<(CM*OUTC + 255)/256, 256>>>(w);
    k_agg<<<PTS/8, 256>>>(x, nidx, kern);
    k_gemm_hmma<<<PTS/128, 256>>>(bias, feat, out);
}

// round 8
// speedup vs baseline: 2.2428x; 1.0520x over previous
#include <cuda_runtime.h>
#include <cuda_fp16.h>
#include <float.h>
#include <cstdint>

#define B_   8
#define C_   64
#define N_   4096
#define K_   20
#define M_   8
#define OUTC 64
#define CM   512          // C_*M_
#define PTS  (B_*N_)      // 32768

// Scratch (allocation-free rule: __device__ globals)
__device__ __align__(16) __half g_ftH[B_*N_*C_];           // feature fp16 [b][n][c] (4 MB)
__device__ __align__(16) __half g_aggH[(size_t)PTS*CM];    // agg fp16 [pt][j]      (32 MB)
__device__ __align__(16) __half g_wh[CM*OUTC];             // conv_w fp16 [oc][j]   (64 KB)

__device__ __forceinline__ uint32_t smem_u32(const void* p) {
    uint32_t a;
    asm("{ .reg .u64 t; cvta.to.shared.u64 t, %1; cvt.u32.u64 %0, t; }" : "=r"(a) : "l"(p));
    return a;
}
// packed f32x2 FMA (sm_100-family base PTX; legal in compute_103)
__device__ __forceinline__ void ffma2(unsigned long long& d,
                                      unsigned long long a, unsigned long long b) {
    asm("fma.rn.f32x2 %0, %1, %2, %0;" : "+l"(d) : "l"(a), "l"(b));
}
__device__ __forceinline__ unsigned long long pack2(float x, float y) {
    unsigned long long r;
    asm("mov.b64 %0, {%1, %2};" : "=l"(r) : "f"(x), "f"(y));
    return r;
}
__device__ __forceinline__ float2 unpack2(unsigned long long v) {
    float2 f;
    asm("mov.b64 {%0, %1}, %2;" : "=f"(f.x), "=f"(f.y) : "l"(v));
    return f;
}

// ===========================================================================
// K1: feature (B,C,N) fp32 -> g_ftH (B,N,C) fp16
// ===========================================================================
__global__ void k_transpose_feat(const float* __restrict__ feat) {
    __shared__ float tile[32][33];
    const int b  = blockIdx.z;
    const int c0 = blockIdx.y * 32;
    const int n0 = blockIdx.x * 32;
    const int tx = threadIdx.x, ty = threadIdx.y;   // block (32,8)
    const float* fb = feat + (size_t)b * C_ * N_;
    #pragma unroll
    for (int r = 0; r < 4; r++)
        tile[ty + 8*r][tx] = fb[(size_t)(c0 + ty + 8*r) * N_ + (n0 + tx)];
    __syncthreads();
    __half* ob = g_ftH + (size_t)b * N_ * C_;
    #pragma unroll
    for (int r = 0; r < 4; r++)
        ob[(size_t)(n0 + ty + 8*r) * C_ + (c0 + tx)] = __float2half(tile[tx][ty + 8*r]);
}

// ===========================================================================
// K2: conv_w fp32 [oc][j] -> fp16 g_wh (same layout)
// ===========================================================================
__global__ void k_prep_w(const float* __restrict__ w) {
    int i = blockIdx.x * blockDim.x + threadIdx.x;
    if (i < CM * OUTC) g_wh[i] = __float2half(w[i]);
}

// ===========================================================================
// K3: warp-per-point: perm matrix + softmax + aggregation -> g_aggH[pt][j]
//     inner loop on packed f32x2 FMA
// ===========================================================================
__global__ void __launch_bounds__(256) k_agg(
    const float* __restrict__ x,
    const int* __restrict__ nidx,          // int32 (JAX x64 disabled)
    const float* __restrict__ kern)
{
    const int warp = threadIdx.x >> 5;
    const int lane = threadIdx.x & 31;
    const int pt   = blockIdx.x * 8 + warp;
    const int b    = pt >> 12;

    __shared__ int   idx_s[8][20];
    __shared__ float p_s[8][20][8];

    float px[8];
    float x0 = 0.f, x1 = 0.f, x2 = 0.f;
    if (lane < K_) {
        int ik = nidx[pt * K_ + lane] & (N_ - 1);
        idx_s[warp][lane] = ik;
        const float* xb = x + (size_t)b * 3 * N_;
        x0 = xb[ik];
        x1 = xb[N_ + ik];
        x2 = xb[2*N_ + ik];
    }
    const float r0 = x0 - __shfl_sync(0xFFFFFFFFu, x0, 0);
    const float r1 = x1 - __shfl_sync(0xFFFFFFFFu, x1, 0);
    const float r2 = x2 - __shfl_sync(0xFFFFFFFFu, x2, 0);

    #pragma unroll
    for (int m = 0; m < M_; m++) {
        float v = r0 * kern[m] + r1 * kern[M_ + m] + r2 * kern[2*M_ + m];
        if (lane == 0 && m == 0) v += 1.0f;       // one_pad
        px[m] = (lane < K_) ? v : -FLT_MAX;
    }

    #pragma unroll
    for (int m = 0; m < M_; m++) {
        float mx = px[m];
        #pragma unroll
        for (int o = 16; o > 0; o >>= 1)
            mx = fmaxf(mx, __shfl_xor_sync(0xFFFFFFFFu, mx, o));
        float e = (lane < K_) ? __expf(px[m] - mx) : 0.f;
        float s = e;
        #pragma unroll
        for (int o = 16; o > 0; o >>= 1)
            s += __shfl_xor_sync(0xFFFFFFFFu, s, o);
        px[m] = e * (1.0f / s);
    }
    if (lane < K_) {
        float4* dst = (float4*)p_s[warp][lane];
        dst[0] = make_float4(px[0], px[1], px[2], px[3]);
        dst[1] = make_float4(px[4], px[5], px[6], px[7]);
    }
    __syncwarp();

    // aggregation: lane owns channels 2*lane, 2*lane+1 (fp16 gather, f32x2 math)
    const int c0 = lane * 2;
    unsigned long long accA[4] = {0,0,0,0};   // channel c0,   m pairs
    unsigned long long accB[4] = {0,0,0,0};   // channel c0+1
    const __half* ftb = g_ftH + (size_t)b * N_ * C_;
    union f4u { float4 v; unsigned long long u[2]; };

    #pragma unroll
    for (int k = 0; k < K_; k++) {
        const int ii = idx_s[warp][k];
        const float2 f = __half22float2(*(const __half2*)(ftb + (size_t)ii * C_ + c0));
        const unsigned long long fxx = pack2(f.x, f.x);
        const unsigned long long fyy = pack2(f.y, f.y);
        f4u pa, pb;
        pa.v = *((const float4*)p_s[warp][k]);
        pb.v = *((const float4*)p_s[warp][k] + 1);
        ffma2(accA[0], fxx, pa.u[0]);  ffma2(accA[1], fxx, pa.u[1]);
        ffma2(accA[2], fxx, pb.u[0]);  ffma2(accA[3], fxx, pb.u[1]);
        ffma2(accB[0], fyy, pa.u[0]);  ffma2(accB[1], fyy, pa.u[1]);
        ffma2(accB[2], fyy, pb.u[0]);  ffma2(accB[3], fyy, pb.u[1]);
    }

    // fp16 pack: lane's 16 values are j = 16*lane .. 16*lane+15
    __half2 h0[4], h1[4];
    #pragma unroll
    for (int i = 0; i < 4; i++) {
        const float2 fa = unpack2(accA[i]);
        const float2 fb = unpack2(accB[i]);
        h0[i] = __floats2half2_rn(fa.x, fa.y);
        h1[i] = __floats2half2_rn(fb.x, fb.y);
    }
    __half* dst = g_aggH + (size_t)pt * CM + 16 * lane;
    *(uint4*)(dst)     = *(uint4*)h0;
    *(uint4*)(dst + 8) = *(uint4*)h1;
}

// ===========================================================================
// K4: HMMA fp16 GEMM, 64pt x 64oc tiles (grid 512), cp.async double buffer
// ===========================================================================
#define AS_STRIDE 72
#define BS_STRIDE 72
#define OS_STRIDE 68

struct Stage { __half a[64 * AS_STRIDE]; __half b[64 * BS_STRIDE]; };

__global__ void __launch_bounds__(256) k_gemm_hmma(
    const float* __restrict__ bias,
    const float* __restrict__ feat,
    float* __restrict__ out)
{
    __shared__ union {
        Stage st[2];
        float o[64 * OS_STRIDE];
    } sm;

    const int tid  = threadIdx.x;
    const int wid  = tid >> 5;
    const int lane = tid & 31;
    const int warp_m = (wid & 3) * 16;   // 4 warps over 64 pts
    const int warp_n = (wid >> 2) * 32;  // 2 warps over 64 ocs
    const int ptBase = blockIdx.x * 64;

    float acc[4][4];
    #pragma unroll
    for (int ni = 0; ni < 4; ni++)
        #pragma unroll
        for (int r = 0; r < 4; r++) acc[ni][r] = 0.f;

    const __half* aSrc = g_aggH + (size_t)ptBase * CM;

    // cp.async chunk loader: 64x64 halves A + 64x64 halves B (2+2 uint4/thread)
    auto load_chunk = [&](int s, int kc) {
        #pragma unroll
        for (int i = 0; i < 2; i++) {
            const int c   = tid + i * 256;
            const int row = c >> 3;
            const int c8  = c & 7;
            asm volatile("cp.async.cg.shared.global [%0], [%1], 16;" ::
                "r"(smem_u32(sm.st[s].a + row * AS_STRIDE + c8 * 8)),
                "l"(aSrc + (size_t)row * CM + kc + c8 * 8));
        }
        #pragma unroll
        for (int i = 0; i < 2; i++) {
            const int c   = tid + i * 256;
            const int row = c >> 3;
            const int c8  = c & 7;
            asm volatile("cp.async.cg.shared.global [%0], [%1], 16;" ::
                "r"(smem_u32(sm.st[s].b + row * BS_STRIDE + c8 * 8)),
                "l"(g_wh + (size_t)row * CM + kc + c8 * 8));
        }
    };

    load_chunk(0, 0);
    asm volatile("cp.async.commit_group;");

    for (int kc8 = 0; kc8 < 8; kc8++) {
        if (kc8 < 7) {
            load_chunk((kc8 + 1) & 1, (kc8 + 1) * 64);
            asm volatile("cp.async.commit_group;");
            asm volatile("cp.async.wait_group 1;");
        } else {
            asm volatile("cp.async.wait_group 0;");
        }
        __syncthreads();

        const Stage& st = sm.st[kc8 & 1];
        #pragma unroll
        for (int ks = 0; ks < 4; ks++) {
            uint32_t a[4];
            {
                const uint32_t addr = smem_u32(
                    st.a + (warp_m + (lane & 15)) * AS_STRIDE
                         + ks * 16 + (lane >> 4) * 8);
                asm volatile("ldmatrix.sync.aligned.m8n8.x4.shared.b16 "
                             "{%0,%1,%2,%3}, [%4];"
                             : "=r"(a[0]), "=r"(a[1]), "=r"(a[2]), "=r"(a[3])
                             : "r"(addr));
            }
            uint32_t bfr[4][2];
            #pragma unroll
            for (int ni = 0; ni < 4; ni++) {
                const uint32_t addr = smem_u32(
                    st.b + (warp_n + ni * 8 + (lane & 7)) * BS_STRIDE
                         + ks * 16 + ((lane >> 3) & 1) * 8);
                asm volatile("ldmatrix.sync.aligned.m8n8.x2.shared.b16 "
                             "{%0,%1}, [%2];"
                             : "=r"(bfr[ni][0]), "=r"(bfr[ni][1])
                             : "r"(addr));
            }
            #pragma unroll
            for (int ni = 0; ni < 4; ni++) {
                asm volatile(
                    "mma.sync.aligned.m16n8k16.row.col.f32.f16.f16.f32 "
                    "{%0,%1,%2,%3}, {%4,%5,%6,%7}, {%8,%9}, {%0,%1,%2,%3};"
                    : "+f"(acc[ni][0]), "+f"(acc[ni][1]),
                      "+f"(acc[ni][2]), "+f"(acc[ni][3])
                    : "r"(a[0]), "r"(a[1]), "r"(a[2]), "r"(a[3]),
                      "r"(bfr[ni][0]), "r"(bfr[ni][1]));
            }
        }
        __syncthreads();
    }

    // scatter fragments to smem as [oc][pt]
    {
        const int r  = lane >> 2;
        const int cp = (lane & 3) * 2;
        #pragma unroll
        for (int ni = 0; ni < 4; ni++) {
            const int pt0 = warp_m + r;
            const int oc0 = warp_n + ni * 8 + cp;
            sm.o[oc0 * OS_STRIDE + pt0]           = acc[ni][0];
            sm.o[(oc0 + 1) * OS_STRIDE + pt0]     = acc[ni][1];
            sm.o[oc0 * OS_STRIDE + pt0 + 8]       = acc[ni][2];
            sm.o[(oc0 + 1) * OS_STRIDE + pt0 + 8] = acc[ni][3];
        }
    }
    __syncthreads();

    // fused epilogue: bias + leaky_relu + residual, coalesced float4 stores
    const int b  = ptBase >> 12;
    const int n0 = ptBase & (N_ - 1);
    #pragma unroll
    for (int i = 0; i < 4; i++) {
        const int c    = tid + i * 256;    // 1024 float4 tasks
        const int oc   = c >> 4;
        const int col4 = (c & 15) * 4;
        const float* src = sm.o + oc * OS_STRIDE + col4;
        const size_t o = ((size_t)(b * OUTC + oc)) * N_ + n0 + col4;
        const float4 f = *(const float4*)(feat + o);
        const float bb = bias[oc];
        float4 v;
        v.x = src[0] + bb; v.x = (v.x > 0.f ? v.x : 0.2f * v.x) + f.x;
        v.y = src[1] + bb; v.y = (v.y > 0.f ? v.y : 0.2f * v.y) + f.y;
        v.z = src[2] + bb; v.z = (v.z > 0.f ? v.z : 0.2f * v.z) + f.z;
        v.w = src[3] + bb; v.w = (v.w > 0.f ? v.w : 0.2f * v.w) + f.w;
        *(float4*)(out + o) = v;
    }
}

// ===========================================================================
extern "C" void kernel_launch(void* const* d_in, const int* in_sizes, int n_in,
                              void* d_out, int out_size) {
    const float* x    = (const float*)d_in[0];
    const float* feat = (const float*)d_in[1];
    const int*   nidx = (const int*)d_in[2];     // int32: JAX x64 is disabled
    const float* kern = (const float*)d_in[3];
    const float* w    = (const float*)d_in[4];
    const float* bias = (const float*)d_in[5];
    float* out = (float*)d_out;

    k_transpose_feat<<<dim3(N_/32, C_/32, B_), dim3(32, 8)>>>(feat);
    k_prep_w<<<(CM*OUTC + 255)/256, 256>>>(w);
    k_agg<<<PTS/8, 256>>>(x, nidx, kern);
    k_gemm_hmma<<<PTS/64, 256>>>(bias, feat, out);
}